// round 13
// baseline (speedup 1.0000x reference)
#include <cuda_runtime.h>
#include <cuda_fp16.h>
#include <cstdint>

// Problem constants: S=2048, B=32, D=256, H=4.  M = S*B = 65536 rows.
#define MROWS 65536
static constexpr size_t MD_ = 16777216ull;   // 65536*256

__device__ float g_pool[8ull * 16777216ull + 4194304ull];

static constexpr size_t O_SMALL = 8ull * 16777216ull;
static constexpr size_t O_SSUM  = O_SMALL;
static constexpr size_t O_SSQ   = O_SMALL + 256;
static constexpr size_t O_SCALE = O_SMALL + 512;
static constexpr size_t O_SHIFT = O_SMALL + 768;
static constexpr size_t O_PM    = O_SMALL + 1024;
static constexpr size_t O_PZ    = O_PM + 32 * 32 * 256;
static constexpr size_t O_PA    = O_PZ + 32 * 32 * 256;
static constexpr size_t O_XCAT  = O_PA + 32 * 32 * 256;
static constexpr size_t O_H0    = O_XCAT + 32 * 1024;
static constexpr size_t O_H1    = O_H0 + 32 * 256;
static constexpr size_t O_WF16  = O_SMALL + 1048576;          // 20 x 65536 fp16
static constexpr size_t O_WSUB  = O_WF16 + 655360;            // 4 x 256x512 fp16
static constexpr size_t O_BSUB  = O_WSUB + 262144;            // 4 x 256 floats

// ---------------------------------------------------------------------------
__device__ __forceinline__ uint32_t s2u(const void* p) {
    uint32_t a;
    asm("{ .reg .u64 t; cvta.to.shared.u64 t, %1; cvt.u32.u64 %0, t; }" : "=r"(a) : "l"(p));
    return a;
}
__device__ __forceinline__ void mma16816(float* d, const uint32_t* a, const uint32_t* b) {
    asm volatile(
        "mma.sync.aligned.m16n8k16.row.col.f32.f16.f16.f32 "
        "{%0,%1,%2,%3}, {%4,%5,%6,%7}, {%8,%9}, {%0,%1,%2,%3};"
        : "+f"(d[0]), "+f"(d[1]), "+f"(d[2]), "+f"(d[3])
        : "r"(a[0]), "r"(a[1]), "r"(a[2]), "r"(a[3]), "r"(b[0]), "r"(b[1]));
}
__device__ __forceinline__ void ldsm4(uint32_t* r, uint32_t a) {
    asm volatile("ldmatrix.sync.aligned.m8n8.x4.shared.b16 {%0,%1,%2,%3}, [%4];"
        : "=r"(r[0]), "=r"(r[1]), "=r"(r[2]), "=r"(r[3]) : "r"(a));
}
__device__ __forceinline__ void cpasync16(uint32_t dst, const void* src) {
    asm volatile("cp.async.cg.shared.global [%0], [%1], 16;" :: "r"(dst), "l"(src));
}
__device__ __forceinline__ void cpcommit() { asm volatile("cp.async.commit_group;"); }
#define CPWAIT(n) asm volatile("cp.async.wait_group %0;" :: "n"(n) : "memory")
#define STS128(a, v)                                                            \
    asm volatile("st.shared.v4.b32 [%0], {%1,%2,%3,%4};"                        \
        :: "r"(a), "r"((v).x), "r"((v).y), "r"((v).z), "r"((v).w) : "memory")

// SMEM: 0..2047 stats; then 4 stages of { A_hi 4KB | A_lo 4KB | W 16KB } = 24KB
#define STG_ALO   4096u
#define STG_W     8192u
#define STG_SIZE  24576u
#define GEMM_SMEM (2048 + 4 * 24576)   // 100352 bytes -> 2 CTAs/SM

// ---------------------------------------------------------------------------
// Core HMMA GEMM: tile M=64 x N=256, 256 threads (8 warps, 2x4), warp 32x64.
// fp16 2-term: D += Ahi*W + Alo*W.  4-stage cp.async ring, 1 barrier/chunk.
// K512: K-dim = 512; chunks 0-7 read A, chunks 8-15 read A2; weight rows
// are 512 wide ([Wk | -Wq] fused).  BN: relu(a*ascale+ashift) on the fly.
// STATS: per-column sum/sumsq of C via shuffle + smem + global atomics.
// ---------------------------------------------------------------------------
template<bool BN, bool STATS, bool K512>
__device__ __forceinline__ void gemm_core(
    const float* __restrict__ A,
    const float* __restrict__ A2,
    const __half* __restrict__ Wh,
    const float* __restrict__ bias,
    const float* __restrict__ ascale,
    const float* __restrict__ ashift,
    float* __restrict__ C,
    float* __restrict__ gsum, float* __restrict__ gsq)
{
    constexpr int NC = K512 ? 16 : 8;
    constexpr int WSTRIDE = K512 ? 512 : 256;

    extern __shared__ __align__(16) char smem[];
    const uint32_t sb = s2u(smem);
    const int t = threadIdx.x, w = t >> 5, l = t & 31;
    const int wr = w >> 2, wc = w & 3;
    const size_t r0 = (size_t)blockIdx.x * 64;

    if (STATS) {
        ((float*)smem)[t] = 0.f;
        ((float*)smem)[t + 256] = 0.f;
    }

    const uint32_t stg0 = sb + 2048;

    const int arow = t >> 2, ag = t & 3;
    const uint32_t a_sts = (uint32_t)(arow * 64 + ((ag ^ ((arow >> 1) & 3)) << 4));
    const int wrow = t >> 2, wg = t & 3;
    const uint32_t w_sts = (uint32_t)(wrow * 64) + (uint32_t)((wg ^ ((wrow >> 1) & 3)) << 4);

    const int a_base_row = wr * 32 + (l & 15);
    const int sa = (a_base_row >> 1) & 3;
    const uint32_t a_off0 = (uint32_t)(a_base_row * 64);
    const int b_base_row = wc * 64 + ((l >> 4) << 3) + (l & 7);
    const int sbz = (b_base_row >> 1) & 3;
    const uint32_t b_off0 = (uint32_t)(b_base_row * 64);
    const int a_gl = l >> 4;
    const int b_gl = (l >> 3) & 1;

    float acc[2][8][4];
#pragma unroll
    for (int mt = 0; mt < 2; mt++)
#pragma unroll
        for (int nt = 0; nt < 8; nt++)
#pragma unroll
            for (int j = 0; j < 4; j++) acc[mt][nt][j] = 0.f;

    float af[8];

    auto fetchW = [&](int ch, uint32_t stg) {
        size_t ws = (size_t)wrow * WSTRIDE + ch * 32 + wg * 8;
#pragma unroll
        for (int j = 0; j < 4; j++)
            cpasync16(stg + STG_W + w_sts + j * 4096u, Wh + ws + (size_t)j * 64 * WSTRIDE);
    };
    auto ldA = [&](int ch) {
        const float* base = (K512 && ch >= 8) ? A2 : A;
        const int cc = K512 ? (ch & 7) : ch;
        const float4* p = (const float4*)(base + (r0 + arow) * 256 + cc * 32 + ag * 8);
        float4 v0 = p[0], v1 = p[1];
        af[0] = v0.x; af[1] = v0.y; af[2] = v0.z; af[3] = v0.w;
        af[4] = v1.x; af[5] = v1.y; af[6] = v1.z; af[7] = v1.w;
        if (BN) {
            int kk = cc * 32 + ag * 8;
#pragma unroll
            for (int i = 0; i < 8; i++)
                af[i] = fmaxf(fmaf(af[i], ascale[kk + i], ashift[kk + i]), 0.f);
        }
    };
    auto stsA = [&](uint32_t stg) {
        uint4 hv, lv;
        __half2* hp = (__half2*)&hv;
        __half2* lp = (__half2*)&lv;
#pragma unroll
        for (int i = 0; i < 4; i++) {
            __half h0 = __float2half(af[2 * i]);
            __half h1 = __float2half(af[2 * i + 1]);
            hp[i].x = h0; hp[i].y = h1;
            lp[i].x = __float2half(af[2 * i]     - __half2float(h0));
            lp[i].y = __float2half(af[2 * i + 1] - __half2float(h1));
        }
        STS128(stg + a_sts, hv);
        STS128(stg + STG_ALO + a_sts, lv);
    };

    // ===== prologue: chunks 0 and 1 =====
    ldA(0); fetchW(0, stg0);              cpcommit(); stsA(stg0);
    ldA(1); fetchW(1, stg0 + STG_SIZE);   cpcommit(); stsA(stg0 + STG_SIZE);

    // ===== mainloop: NC chunks of k32, 4-stage ring, 1 barrier/chunk =====
    for (int c = 0; c < NC; c++) {
        const uint32_t stgs = stg0 + (uint32_t)(c & 3) * STG_SIZE;
        const uint32_t stgn = stg0 + (uint32_t)((c + 2) & 3) * STG_SIZE;

        if (c + 2 < NC) {
            ldA(c + 2);
            fetchW(c + 2, stgn);
            cpcommit();
        }
        if (c <= NC - 3) { CPWAIT(2); } else if (c == NC - 2) { CPWAIT(1); } else { CPWAIT(0); }
        __syncthreads();
        if (c + 2 < NC) stsA(stgn);   // readers are 2 barriers away

#pragma unroll
        for (int ks = 0; ks < 2; ks++) {
            uint32_t ah[2][4], al[2][4], bb[4];
            const uint32_t agoff = (uint32_t)(((ks * 2 + a_gl) ^ sa) << 4);
            ldsm4(ah[0], stgs + a_off0 + agoff);
            ldsm4(ah[1], stgs + a_off0 + 1024 + agoff);
            ldsm4(al[0], stgs + STG_ALO + a_off0 + agoff);
            ldsm4(al[1], stgs + STG_ALO + a_off0 + 1024 + agoff);
            const uint32_t bgoff = (uint32_t)(((ks * 2 + b_gl) ^ sbz) << 4);
#pragma unroll
            for (int n2 = 0; n2 < 4; n2++) {
                const uint32_t brow = b_off0 + (uint32_t)(n2 * 1024);
                ldsm4(bb, stgs + STG_W + brow + bgoff);
                mma16816(acc[0][n2 * 2],     ah[0], bb);
                mma16816(acc[0][n2 * 2 + 1], ah[0], bb + 2);
                mma16816(acc[1][n2 * 2],     ah[1], bb);
                mma16816(acc[1][n2 * 2 + 1], ah[1], bb + 2);
                mma16816(acc[0][n2 * 2],     al[0], bb);
                mma16816(acc[0][n2 * 2 + 1], al[0], bb + 2);
                mma16816(acc[1][n2 * 2],     al[1], bb);
                mma16816(acc[1][n2 * 2 + 1], al[1], bb + 2);
            }
        }
    }

    // ===== epilogue =====
    const int erow = wr * 32 + (l >> 2);
#pragma unroll
    for (int nt = 0; nt < 8; nt++) {
        const int col = wc * 64 + nt * 8 + (l & 3) * 2;
        const float2 bb2 = *(const float2*)(bias + col);
        float s0 = 0.f, s1 = 0.f, q0 = 0.f, q1 = 0.f;
#pragma unroll
        for (int mt = 0; mt < 2; mt++) {
            const size_t row = r0 + erow + mt * 16;
            float v0 = acc[mt][nt][0] + bb2.x;
            float v1 = acc[mt][nt][1] + bb2.y;
            float v2 = acc[mt][nt][2] + bb2.x;
            float v3 = acc[mt][nt][3] + bb2.y;
            *(float2*)(C + row * 256 + col)       = make_float2(v0, v1);
            *(float2*)(C + (row + 8) * 256 + col) = make_float2(v2, v3);
            if (STATS) {
                s0 += v0 + v2; s1 += v1 + v3;
                q0 += v0 * v0 + v2 * v2; q1 += v1 * v1 + v3 * v3;
            }
        }
        if (STATS) {
#pragma unroll
            for (int off = 4; off < 32; off <<= 1) {
                s0 += __shfl_xor_sync(0xFFFFFFFFu, s0, off);
                s1 += __shfl_xor_sync(0xFFFFFFFFu, s1, off);
                q0 += __shfl_xor_sync(0xFFFFFFFFu, q0, off);
                q1 += __shfl_xor_sync(0xFFFFFFFFu, q1, off);
            }
            if (l < 4) {
                float* ss = (float*)smem;
                atomicAdd(ss + col,           s0);
                atomicAdd(ss + col + 1,       s1);
                atomicAdd(ss + 256 + col,     q0);
                atomicAdd(ss + 256 + col + 1, q1);
            }
        }
    }

    if (STATS) {
        __syncthreads();
        atomicAdd(gsum + t, ((float*)smem)[t]);
        atomicAdd(gsq  + t, ((float*)smem)[256 + t]);
    }
}

// ---- wrappers ----
// One launch computes Q, K, V projections AND W = K-Q (via fused [Wk|-Wq],
// K=512) as four independent units -> no Q->KV serialization.
__global__ __launch_bounds__(256, 2)
void gemm_proj(const float* Qs, const float* Ks, const float* Vs,
               const __half* wq_, const __half* wk_, const __half* wv_,
               const __half* wsub,
               const float* bq_, const float* bk_, const float* bv_,
               const float* bsub,
               float* Qd, float* Kd, float* Vd, float* Wbuf,
               float* gsum, float* gsq)
{
    const int u = blockIdx.y;
    if (u == 0)
        gemm_core<false, false, false>(Qs, nullptr, wq_, bq_, nullptr, nullptr,
                                       Qd, nullptr, nullptr);
    else if (u == 1)
        gemm_core<false, false, false>(Ks, nullptr, wk_, bk_, nullptr, nullptr,
                                       Kd, nullptr, nullptr);
    else if (u == 2)
        gemm_core<false, false, false>(Vs, nullptr, wv_, bv_, nullptr, nullptr,
                                       Vd, nullptr, nullptr);
    else
        gemm_core<false, true, true>(Ks, Qs, wsub, bsub, nullptr, nullptr,
                                     Wbuf, gsum, gsq);
}
__global__ __launch_bounds__(256, 2)
void gemm_bn_stats(const float* A, const __half* Wh, const float* bias,
                   const float* ascale, const float* ashift,
                   float* C, float* gsum, float* gsq)
{
    gemm_core<true, true, false>(A, nullptr, Wh, bias, ascale, ashift,
                                 C, gsum, gsq);
}
__global__ __launch_bounds__(256, 2)
void gemm_bn(const float* A, const __half* Wh, const float* bias,
             const float* ascale, const float* ashift, float* C)
{
    gemm_core<true, false, false>(A, nullptr, Wh, bias, ascale, ashift,
                                  C, nullptr, nullptr);
}

// ---------------------------------------------------------------------------
__global__ void wconv(const float* __restrict__ w0, const float* __restrict__ w1,
                      const float* __restrict__ w2, const float* __restrict__ w3,
                      const float* __restrict__ w4, __half* __restrict__ out)
{
    size_t i = (size_t)blockIdx.x * 256 + threadIdx.x;
    size_t a = i >> 18, r = i & 262143;
    const float* s = (a == 0) ? w0 : (a == 1) ? w1 : (a == 2) ? w2 : (a == 3) ? w3 : w4;
    out[i] = __float2half(s[r]);
}

// Fused subtraction weights: per head h, rows n=0..255 of [Wk[h] | -Wq[h]] (512 wide)
__global__ void wsubconv(const float* __restrict__ wq, const float* __restrict__ wk,
                         __half* __restrict__ out)
{
    size_t i = (size_t)blockIdx.x * 256 + threadIdx.x;   // < 524288
    size_t h = i >> 17, rem = i & 131071;
    int n = (int)(rem >> 9), j = (int)(rem & 511);
    float v = (j < 256) ? wk[h * 65536 + n * 256 + j]
                        : -wq[h * 65536 + n * 256 + (j - 256)];
    out[i] = __float2half(v);
}
__global__ void bsubk(const float* __restrict__ bq, const float* __restrict__ bk,
                      float* __restrict__ out)
{
    int i = blockIdx.x * 256 + threadIdx.x;   // < 1024
    out[i] = bk[i] - bq[i];
}

// bnfinal: consume stats, produce scale/shift, re-zero accumulators.
__global__ void bnfinal(float* __restrict__ s, float* __restrict__ sq,
                        const float* __restrict__ gamma, const float* __restrict__ beta,
                        float* __restrict__ scale, float* __restrict__ shift)
{
    int c = threadIdx.x;
    const float inv = 1.f / 65536.f;
    float m = s[c] * inv;
    float v = sq[c] * inv - m * m;
    float r = rsqrtf(v + 1e-5f);
    float sc = r * gamma[c];
    scale[c] = sc;
    shift[c] = beta[c] - m * sc;
    s[c] = 0.f;
    sq[c] = 0.f;
}

// Online softmax over S fused with weighted V-sum (32-way split over S)
__global__ void smax_part(const float* __restrict__ W3, const float* __restrict__ V,
                          float* __restrict__ pm, float* __restrict__ pz,
                          float* __restrict__ pa)
{
    int b = blockIdx.x, ch = blockIdx.y, d = threadIdx.x;
    float m = -1e30f, Z = 0.f, acc = 0.f;
#pragma unroll 4
    for (int j = 0; j < 64; j++) {
        int s_ = ch * 64 + j;
        size_t idx = ((size_t)(s_ * 32 + b)) * 256 + d;
        float w = W3[idx];
        float v = V[idx];
        float nm = fmaxf(m, w);
        float e0 = __expf(m - nm);
        float e1 = __expf(w - nm);
        Z = Z * e0 + e1;
        acc = fmaf(v, e1, acc * e0);
        m = nm;
    }
    int o = (ch * 32 + b) * 256 + d;
    pm[o] = m; pz[o] = Z; pa[o] = acc;
}

__global__ void smax_comb(const float* __restrict__ pm, const float* __restrict__ pz,
                          const float* __restrict__ pa, float* __restrict__ xcat,
                          int head)
{
    int b = blockIdx.x, d = threadIdx.x;
    float m = -1e30f, Z = 0.f, acc = 0.f;
#pragma unroll
    for (int ch = 0; ch < 32; ch++) {
        int o = (ch * 32 + b) * 256 + d;
        float cm = pm[o];
        float nm = fmaxf(m, cm);
        float e0 = __expf(m - nm);
        float e1 = __expf(cm - nm);
        Z = Z * e0 + pz[o] * e1;
        acc = acc * e0 + pa[o] * e1;
        m = nm;
    }
    xcat[b * 1024 + head * 256 + d] = acc / Z;
}

__global__ void mlp_k(const float* __restrict__ X, const float* __restrict__ Wm,
                      const float* __restrict__ bias, float* __restrict__ Y,
                      int Kdim, int do_relu)
{
    __shared__ float sx[1024];
    int b = blockIdx.x, c = threadIdx.x;
    for (int t = c; t < Kdim; t += 256) sx[t] = X[b * Kdim + t];
    __syncthreads();
    float s = 0.f;
#pragma unroll 4
    for (int t = 0; t < Kdim; t++) s = fmaf(sx[t], Wm[c * Kdim + t], s);
    s += bias[c];
    if (do_relu) s = fmaxf(s, 0.f);
    Y[b * 256 + c] = s;
}

// ---------------------------------------------------------------------------
extern "C" void kernel_launch(void* const* d_in, const int* in_sizes, int n_in,
                              void* d_out, int out_size)
{
    float* pool = nullptr;
    cudaGetSymbolAddress((void**)&pool, g_pool);

    cudaFuncSetAttribute(gemm_proj,     cudaFuncAttributeMaxDynamicSharedMemorySize, GEMM_SMEM);
    cudaFuncSetAttribute(gemm_bn_stats, cudaFuncAttributeMaxDynamicSharedMemorySize, GEMM_SMEM);
    cudaFuncSetAttribute(gemm_bn,       cudaFuncAttributeMaxDynamicSharedMemorySize, GEMM_SMEM);

    const float* q   = (const float*)d_in[0];
    const float* k   = (const float*)d_in[1];
    const float* v   = (const float*)d_in[2];
    const float* wq  = (const float*)d_in[3];
    const float* bq  = (const float*)d_in[4];
    const float* wk  = (const float*)d_in[5];
    const float* bk  = (const float*)d_in[6];
    const float* wv  = (const float*)d_in[7];
    const float* bv  = (const float*)d_in[8];
    const float* g1  = (const float*)d_in[9];
    const float* be1 = (const float*)d_in[10];
    const float* wl1 = (const float*)d_in[11];
    const float* bl1 = (const float*)d_in[12];
    const float* g2  = (const float*)d_in[13];
    const float* be2 = (const float*)d_in[14];
    const float* wl2 = (const float*)d_in[15];
    const float* bl2 = (const float*)d_in[16];
    const float* mw0 = (const float*)d_in[17];
    const float* mb0 = (const float*)d_in[18];
    const float* mw1 = (const float*)d_in[19];
    const float* mb1 = (const float*)d_in[20];
    const float* mw2 = (const float*)d_in[21];
    const float* mb2 = (const float*)d_in[22];

    float* Qb[2] = {pool + 0 * MD_, pool + 1 * MD_};
    float* Kb[2] = {pool + 2 * MD_, pool + 3 * MD_};
    float* Vb[2] = {pool + 4 * MD_, pool + 5 * MD_};
    float* W     = pool + 6 * MD_;
    float* W2    = pool + 7 * MD_;
    float* ssum  = pool + O_SSUM;
    float* ssq   = pool + O_SSQ;
    float* scale = pool + O_SCALE;
    float* shift = pool + O_SHIFT;
    float* pm    = pool + O_PM;
    float* pz    = pool + O_PZ;
    float* pa    = pool + O_PA;
    float* xcat  = pool + O_XCAT;
    float* h0    = pool + O_H0;
    float* h1    = pool + O_H1;
    __half* wf   = (__half*)(pool + O_WF16);
    __half* wsub = (__half*)(pool + O_WSUB);
    float* bsub  = pool + O_BSUB;

    // weight prep (independent, once per launch)
    wconv<<<5120, 256>>>(wq, wk, wv, wl1, wl2, wf);
    wsubconv<<<2048, 256>>>(wq, wk, wsub);
    bsubk<<<4, 256>>>(bq, bk, bsub);

    const int NT = MROWS / 64;   // 1024 row tiles

    for (int i = 0; i < 4; i++) {
        const float* Qs = i ? Qb[(i - 1) & 1] : q;
        const float* Ks = i ? Kb[(i - 1) & 1] : k;
        const float* Vs = i ? Vb[(i - 1) & 1] : v;
        float* Qd = Qb[i & 1];
        float* Kd = Kb[i & 1];
        float* Vd = Vb[i & 1];

        const __half* whq = wf + (0 * 4 + i) * 65536;
        const __half* whk = wf + (1 * 4 + i) * 65536;
        const __half* whv = wf + (2 * 4 + i) * 65536;
        const __half* wh1 = wf + (3 * 4 + i) * 65536;
        const __half* wh2 = wf + (4 * 4 + i) * 65536;

        gemm_proj<<<dim3(NT, 4), 256, GEMM_SMEM>>>(
            Qs, Ks, Vs, whq, whk, whv, wsub + i * 131072,
            bq + i * 256, bk + i * 256, bv + i * 256, bsub + i * 256,
            Qd, Kd, Vd, W, ssum, ssq);
        bnfinal<<<1, 256>>>(ssum, ssq, g1 + i * 256, be1 + i * 256, scale, shift);

        gemm_bn_stats<<<NT, 256, GEMM_SMEM>>>(W, wh1, bl1 + i * 256,
                                              scale, shift, W2, ssum, ssq);
        bnfinal<<<1, 256>>>(ssum, ssq, g2 + i * 256, be2 + i * 256, scale, shift);

        gemm_bn<<<NT, 256, GEMM_SMEM>>>(W2, wh2, bl2 + i * 256, scale, shift, W);

        smax_part<<<dim3(32, 32), 256>>>(W, Vd, pm, pz, pa);
        smax_comb<<<32, 256>>>(pm, pz, pa, xcat, i);
    }

    mlp_k<<<32, 256>>>(xcat, mw0, mb0, h0, 1024, 1);
    mlp_k<<<32, 256>>>(h0, mw1, mb1, h1, 256, 1);
    mlp_k<<<32, 256>>>(h1, mw2, mb2, (float*)d_out, 256, 0);
}

// round 15
// speedup vs baseline: 1.3429x; 1.3429x over previous
#include <cuda_runtime.h>
#include <cuda_fp16.h>
#include <cstdint>

// Problem constants: S=2048, B=32, D=256, H=4.  M = S*B = 65536 rows.
#define MROWS 65536
static constexpr size_t MD_ = 16777216ull;   // 65536*256

__device__ float g_pool[8ull * 16777216ull + 4194304ull];

static constexpr size_t O_SMALL = 8ull * 16777216ull;
static constexpr size_t O_SSUM  = O_SMALL;
static constexpr size_t O_SSQ   = O_SMALL + 256;
static constexpr size_t O_SCALE = O_SMALL + 512;
static constexpr size_t O_SHIFT = O_SMALL + 768;
static constexpr size_t O_PM    = O_SMALL + 1024;
static constexpr size_t O_PZ    = O_PM + 16 * 32 * 256;
static constexpr size_t O_PA    = O_PZ + 16 * 32 * 256;
static constexpr size_t O_XCAT  = O_PA + 16 * 32 * 256;
static constexpr size_t O_H0    = O_XCAT + 32 * 1024;
static constexpr size_t O_H1    = O_H0 + 32 * 256;
static constexpr size_t O_WF16  = O_SMALL + 1048576;   // fp16 weights (20 * 65536)

// ---------------------------------------------------------------------------
__device__ __forceinline__ uint32_t s2u(const void* p) {
    uint32_t a;
    asm("{ .reg .u64 t; cvta.to.shared.u64 t, %1; cvt.u32.u64 %0, t; }" : "=r"(a) : "l"(p));
    return a;
}
__device__ __forceinline__ void mma16816(float* d, const uint32_t* a, const uint32_t* b) {
    asm volatile(
        "mma.sync.aligned.m16n8k16.row.col.f32.f16.f16.f32 "
        "{%0,%1,%2,%3}, {%4,%5,%6,%7}, {%8,%9}, {%0,%1,%2,%3};"
        : "+f"(d[0]), "+f"(d[1]), "+f"(d[2]), "+f"(d[3])
        : "r"(a[0]), "r"(a[1]), "r"(a[2]), "r"(a[3]), "r"(b[0]), "r"(b[1]));
}
__device__ __forceinline__ void ldsm4(uint32_t* r, uint32_t a) {
    asm volatile("ldmatrix.sync.aligned.m8n8.x4.shared.b16 {%0,%1,%2,%3}, [%4];"
        : "=r"(r[0]), "=r"(r[1]), "=r"(r[2]), "=r"(r[3]) : "r"(a));
}
__device__ __forceinline__ void cpasync16(uint32_t dst, const void* src) {
    asm volatile("cp.async.cg.shared.global [%0], [%1], 16;" :: "r"(dst), "l"(src));
}
__device__ __forceinline__ void cpcommit() { asm volatile("cp.async.commit_group;"); }
#define CPWAIT(n) asm volatile("cp.async.wait_group %0;" :: "n"(n) : "memory")
#define STS128(a, v)                                                            \
    asm volatile("st.shared.v4.b32 [%0], {%1,%2,%3,%4};"                        \
        :: "r"(a), "r"((v).x), "r"((v).y), "r"((v).z), "r"((v).w) : "memory")

// SMEM: 0..2047 stats; then 4 stages of { A 4KB | W 16KB } = 20KB
#define STG_W     4096u
#define STG_SIZE  20480u
#define GEMM_SMEM (2048 + 4 * 20480)   // 83968 bytes -> 2 CTAs/SM

// ---------------------------------------------------------------------------
// Core HMMA GEMM: tile M=64 x N=256, 256 threads (8 warps, 2x4), warp 32x64.
// C = act(A) @ W^T + bias ; act = relu(a*ascale+ashift) if BN.
// Pure fp16 operands (A rounded to fp16 on load, W pre-converted), fp32 accum.
// 4-stage cp.async ring, ONE __syncthreads per 32-k chunk.
// SUB: w = C - Qsub -> Wout, stats on w.  STATS: column sum/sumsq atomics.
// ---------------------------------------------------------------------------
template<bool BN, bool SUB, bool STATS>
__device__ __forceinline__ void gemm_core(
    const float* __restrict__ A,
    const __half* __restrict__ Wh,
    const float* __restrict__ bias,
    const float* __restrict__ ascale,
    const float* __restrict__ ashift,
    float* __restrict__ C,
    const float* __restrict__ Qsub,
    float* __restrict__ Wout,
    float* __restrict__ gsum, float* __restrict__ gsq)
{
    extern __shared__ __align__(16) char smem[];
    const uint32_t sb = s2u(smem);
    const int t = threadIdx.x, w = t >> 5, l = t & 31;
    const int wr = w >> 2, wc = w & 3;
    const size_t r0 = (size_t)blockIdx.x * 64;

    if (STATS) {
        ((float*)smem)[t] = 0.f;
        ((float*)smem)[t + 256] = 0.f;
    }

    const uint32_t stg0 = sb + 2048;

    // loader mapping
    const int arow = t >> 2, ag = t & 3;         // A: 64 rows x 4 granules
    const uint32_t a_sts = (uint32_t)(arow * 64 + ((ag ^ ((arow >> 1) & 3)) << 4));
    const int wrow = t >> 2, wg = t & 3;         // W: rows wrow + 64j
    const uint32_t w_sts = (uint32_t)(wrow * 64) + (uint32_t)((wg ^ ((wrow >> 1) & 3)) << 4);

    // ldmatrix lane constants
    const int a_base_row = wr * 32 + (l & 15);
    const int sa = (a_base_row >> 1) & 3;
    const uint32_t a_off0 = (uint32_t)(a_base_row * 64);
    const int b_base_row = wc * 64 + ((l >> 4) << 3) + (l & 7);
    const int sbz = (b_base_row >> 1) & 3;
    const uint32_t b_off0 = (uint32_t)(b_base_row * 64);
    const int a_gl = l >> 4;
    const int b_gl = (l >> 3) & 1;

    float acc[2][8][4];
#pragma unroll
    for (int mt = 0; mt < 2; mt++)
#pragma unroll
        for (int nt = 0; nt < 8; nt++)
#pragma unroll
            for (int j = 0; j < 4; j++) acc[mt][nt][j] = 0.f;

    float af[8];

    auto fetchW = [&](int ch, uint32_t stg) {
        size_t ws = (size_t)wrow * 256 + ch * 32 + wg * 8;
#pragma unroll
        for (int j = 0; j < 4; j++)
            cpasync16(stg + STG_W + w_sts + j * 4096u, Wh + ws + (size_t)j * 64 * 256);
    };
    auto ldA = [&](int ch) {
        const float4* p = (const float4*)(A + (r0 + arow) * 256 + ch * 32 + ag * 8);
        float4 v0 = p[0], v1 = p[1];
        af[0] = v0.x; af[1] = v0.y; af[2] = v0.z; af[3] = v0.w;
        af[4] = v1.x; af[5] = v1.y; af[6] = v1.z; af[7] = v1.w;
        if (BN) {
            int kk = ch * 32 + ag * 8;
#pragma unroll
            for (int i = 0; i < 8; i++)
                af[i] = fmaxf(fmaf(af[i], ascale[kk + i], ashift[kk + i]), 0.f);
        }
    };
    auto stsA = [&](uint32_t stg) {
        uint4 hv;
        __half2* hp = (__half2*)&hv;
#pragma unroll
        for (int i = 0; i < 4; i++) {
            hp[i].x = __float2half(af[2 * i]);
            hp[i].y = __float2half(af[2 * i + 1]);
        }
        STS128(stg + a_sts, hv);
    };

    // ===== prologue: chunks 0 and 1 =====
    ldA(0); fetchW(0, stg0);              cpcommit(); stsA(stg0);
    ldA(1); fetchW(1, stg0 + STG_SIZE);   cpcommit(); stsA(stg0 + STG_SIZE);

    // ===== mainloop: 8 chunks of k32, 4-stage ring, 1 barrier/chunk =====
    for (int c = 0; c < 8; c++) {
        const uint32_t stgs = stg0 + (uint32_t)(c & 3) * STG_SIZE;
        const uint32_t stgn = stg0 + (uint32_t)((c + 2) & 3) * STG_SIZE;

        if (c < 6) {
            ldA(c + 2);
            fetchW(c + 2, stgn);
            cpcommit();
        }
        if (c <= 5) { CPWAIT(2); } else if (c == 6) { CPWAIT(1); } else { CPWAIT(0); }
        __syncthreads();
        if (c < 6) stsA(stgn);   // readers are 2 barriers away

        // ---- compute chunk c ----
#pragma unroll
        for (int ks = 0; ks < 2; ks++) {
            uint32_t ah[2][4], bb[4];
            const uint32_t agoff = (uint32_t)(((ks * 2 + a_gl) ^ sa) << 4);
            ldsm4(ah[0], stgs + a_off0 + agoff);
            ldsm4(ah[1], stgs + a_off0 + 1024 + agoff);
            const uint32_t bgoff = (uint32_t)(((ks * 2 + b_gl) ^ sbz) << 4);
#pragma unroll
            for (int n2 = 0; n2 < 4; n2++) {
                const uint32_t brow = b_off0 + (uint32_t)(n2 * 1024);
                ldsm4(bb, stgs + STG_W + brow + bgoff);
                mma16816(acc[0][n2 * 2],     ah[0], bb);
                mma16816(acc[0][n2 * 2 + 1], ah[0], bb + 2);
                mma16816(acc[1][n2 * 2],     ah[1], bb);
                mma16816(acc[1][n2 * 2 + 1], ah[1], bb + 2);
            }
        }
    }

    // ===== epilogue =====
    const int erow = wr * 32 + (l >> 2);
#pragma unroll
    for (int nt = 0; nt < 8; nt++) {
        const int col = wc * 64 + nt * 8 + (l & 3) * 2;
        const float2 bb2 = *(const float2*)(bias + col);
        float s0 = 0.f, s1 = 0.f, q0 = 0.f, q1 = 0.f;
#pragma unroll
        for (int mt = 0; mt < 2; mt++) {
            const size_t row = r0 + erow + mt * 16;
            float v0 = acc[mt][nt][0] + bb2.x;
            float v1 = acc[mt][nt][1] + bb2.y;
            float v2 = acc[mt][nt][2] + bb2.x;
            float v3 = acc[mt][nt][3] + bb2.y;
            *(float2*)(C + row * 256 + col)       = make_float2(v0, v1);
            *(float2*)(C + (row + 8) * 256 + col) = make_float2(v2, v3);
            if (SUB) {
                float2 qa = *(const float2*)(Qsub + row * 256 + col);
                float2 qb = *(const float2*)(Qsub + (row + 8) * 256 + col);
                float w0 = v0 - qa.x, w1 = v1 - qa.y;
                float w2 = v2 - qb.x, w3 = v3 - qb.y;
                *(float2*)(Wout + row * 256 + col)       = make_float2(w0, w1);
                *(float2*)(Wout + (row + 8) * 256 + col) = make_float2(w2, w3);
                s0 += w0 + w2; s1 += w1 + w3;
                q0 += w0 * w0 + w2 * w2; q1 += w1 * w1 + w3 * w3;
            } else if (STATS) {
                s0 += v0 + v2; s1 += v1 + v3;
                q0 += v0 * v0 + v2 * v2; q1 += v1 * v1 + v3 * v3;
            }
        }
        if (STATS) {
            // reduce over the 8 lanes (stride 4) sharing this column pair
#pragma unroll
            for (int off = 4; off < 32; off <<= 1) {
                s0 += __shfl_xor_sync(0xFFFFFFFFu, s0, off);
                s1 += __shfl_xor_sync(0xFFFFFFFFu, s1, off);
                q0 += __shfl_xor_sync(0xFFFFFFFFu, q0, off);
                q1 += __shfl_xor_sync(0xFFFFFFFFu, q1, off);
            }
            if (l < 4) {
                float* ss = (float*)smem;
                atomicAdd(ss + col,           s0);
                atomicAdd(ss + col + 1,       s1);
                atomicAdd(ss + 256 + col,     q0);
                atomicAdd(ss + 256 + col + 1, q1);
            }
        }
    }

    if (STATS) {
        __syncthreads();
        atomicAdd(gsum + t, ((float*)smem)[t]);
        atomicAdd(gsq  + t, ((float*)smem)[256 + t]);
    }
}

// ---- wrappers ----
__global__ __launch_bounds__(256, 2)
void gemm_plain(const float* A, const __half* Wh, const float* bias, float* C)
{
    gemm_core<false, false, false>(A, Wh, bias, nullptr, nullptr, C,
                                   nullptr, nullptr, nullptr, nullptr);
}
__global__ __launch_bounds__(256, 2)
void gemm_kv(const float* Ka, const __half* KWh, const float* kb, float* Kd,
             const float* Va, const __half* VWh, const float* vb, float* Vd,
             const float* Qd, float* Wout, float* gsum, float* gsq)
{
    if (blockIdx.y == 0)
        gemm_core<false, true, true>(Ka, KWh, kb, nullptr, nullptr, Kd,
                                     Qd, Wout, gsum, gsq);
    else
        gemm_core<false, false, false>(Va, VWh, vb, nullptr, nullptr, Vd,
                                       nullptr, nullptr, nullptr, nullptr);
}
__global__ __launch_bounds__(256, 2)
void gemm_bn_stats(const float* A, const __half* Wh, const float* bias,
                   const float* ascale, const float* ashift,
                   float* C, float* gsum, float* gsq)
{
    gemm_core<true, false, true>(A, Wh, bias, ascale, ashift, C,
                                 nullptr, nullptr, gsum, gsq);
}
__global__ __launch_bounds__(256, 2)
void gemm_bn(const float* A, const __half* Wh, const float* bias,
             const float* ascale, const float* ashift, float* C)
{
    gemm_core<true, false, false>(A, Wh, bias, ascale, ashift, C,
                                  nullptr, nullptr, nullptr, nullptr);
}

// ---------------------------------------------------------------------------
__global__ void wconv(const float* __restrict__ w0, const float* __restrict__ w1,
                      const float* __restrict__ w2, const float* __restrict__ w3,
                      const float* __restrict__ w4, __half* __restrict__ out)
{
    size_t i = (size_t)blockIdx.x * 256 + threadIdx.x;
    size_t a = i >> 18, r = i & 262143;
    const float* s = (a == 0) ? w0 : (a == 1) ? w1 : (a == 2) ? w2 : (a == 3) ? w3 : w4;
    out[i] = __float2half(s[r]);
}

// bnfinal: consume stats, produce scale/shift, and re-zero accumulators so the
// next accumulation (and the next graph replay) starts from zero.
__global__ void bnfinal(float* __restrict__ s, float* __restrict__ sq,
                        const float* __restrict__ gamma, const float* __restrict__ beta,
                        float* __restrict__ scale, float* __restrict__ shift)
{
    int c = threadIdx.x;
    const float inv = 1.f / 65536.f;
    float m = s[c] * inv;
    float v = sq[c] * inv - m * m;
    float r = rsqrtf(v + 1e-5f);
    float sc = r * gamma[c];
    scale[c] = sc;
    shift[c] = beta[c] - m * sc;
    s[c] = 0.f;
    sq[c] = 0.f;
}

// Online softmax over S fused with weighted V-sum (16-way split over S)
__global__ void smax_part(const float* __restrict__ W3, const float* __restrict__ V,
                          float* __restrict__ pm, float* __restrict__ pz,
                          float* __restrict__ pa)
{
    int b = blockIdx.x, ch = blockIdx.y, d = threadIdx.x;
    float m = -1e30f, Z = 0.f, acc = 0.f;
#pragma unroll 4
    for (int j = 0; j < 128; j++) {
        int s_ = ch * 128 + j;
        size_t idx = ((size_t)(s_ * 32 + b)) * 256 + d;
        float w = W3[idx];
        float v = V[idx];
        float nm = fmaxf(m, w);
        float e0 = __expf(m - nm);
        float e1 = __expf(w - nm);
        Z = Z * e0 + e1;
        acc = fmaf(v, e1, acc * e0);
        m = nm;
    }
    int o = (ch * 32 + b) * 256 + d;
    pm[o] = m; pz[o] = Z; pa[o] = acc;
}

__global__ void smax_comb(const float* __restrict__ pm, const float* __restrict__ pz,
                          const float* __restrict__ pa, float* __restrict__ xcat,
                          int head)
{
    int b = blockIdx.x, d = threadIdx.x;
    float m = -1e30f, Z = 0.f, acc = 0.f;
#pragma unroll
    for (int ch = 0; ch < 16; ch++) {
        int o = (ch * 32 + b) * 256 + d;
        float cm = pm[o];
        float nm = fmaxf(m, cm);
        float e0 = __expf(m - nm);
        float e1 = __expf(cm - nm);
        Z = Z * e0 + pz[o] * e1;
        acc = acc * e0 + pa[o] * e1;
        m = nm;
    }
    xcat[b * 1024 + head * 256 + d] = acc / Z;
}

__global__ void mlp_k(const float* __restrict__ X, const float* __restrict__ Wm,
                      const float* __restrict__ bias, float* __restrict__ Y,
                      int Kdim, int do_relu)
{
    __shared__ float sx[1024];
    int b = blockIdx.x, c = threadIdx.x;
    for (int t = c; t < Kdim; t += 256) sx[t] = X[b * Kdim + t];
    __syncthreads();
    float s = 0.f;
#pragma unroll 4
    for (int t = 0; t < Kdim; t++) s = fmaf(sx[t], Wm[c * Kdim + t], s);
    s += bias[c];
    if (do_relu) s = fmaxf(s, 0.f);
    Y[b * 256 + c] = s;
}

// ---------------------------------------------------------------------------
extern "C" void kernel_launch(void* const* d_in, const int* in_sizes, int n_in,
                              void* d_out, int out_size)
{
    float* pool = nullptr;
    cudaGetSymbolAddress((void**)&pool, g_pool);

    cudaFuncSetAttribute(gemm_plain,    cudaFuncAttributeMaxDynamicSharedMemorySize, GEMM_SMEM);
    cudaFuncSetAttribute(gemm_kv,       cudaFuncAttributeMaxDynamicSharedMemorySize, GEMM_SMEM);
    cudaFuncSetAttribute(gemm_bn_stats, cudaFuncAttributeMaxDynamicSharedMemorySize, GEMM_SMEM);
    cudaFuncSetAttribute(gemm_bn,       cudaFuncAttributeMaxDynamicSharedMemorySize, GEMM_SMEM);

    const float* q   = (const float*)d_in[0];
    const float* k   = (const float*)d_in[1];
    const float* v   = (const float*)d_in[2];
    const float* wq  = (const float*)d_in[3];
    const float* bq  = (const float*)d_in[4];
    const float* wk  = (const float*)d_in[5];
    const float* bk  = (const float*)d_in[6];
    const float* wv  = (const float*)d_in[7];
    const float* bv  = (const float*)d_in[8];
    const float* g1  = (const float*)d_in[9];
    const float* be1 = (const float*)d_in[10];
    const float* wl1 = (const float*)d_in[11];
    const float* bl1 = (const float*)d_in[12];
    const float* g2  = (const float*)d_in[13];
    const float* be2 = (const float*)d_in[14];
    const float* wl2 = (const float*)d_in[15];
    const float* bl2 = (const float*)d_in[16];
    const float* mw0 = (const float*)d_in[17];
    const float* mb0 = (const float*)d_in[18];
    const float* mw1 = (const float*)d_in[19];
    const float* mb1 = (const float*)d_in[20];
    const float* mw2 = (const float*)d_in[21];
    const float* mb2 = (const float*)d_in[22];

    float* Qb[2] = {pool + 0 * MD_, pool + 1 * MD_};
    float* Kb[2] = {pool + 2 * MD_, pool + 3 * MD_};
    float* Vb[2] = {pool + 4 * MD_, pool + 5 * MD_};
    float* W     = pool + 6 * MD_;
    float* W2    = pool + 7 * MD_;
    float* ssum  = pool + O_SSUM;
    float* ssq   = pool + O_SSQ;
    float* scale = pool + O_SCALE;
    float* shift = pool + O_SHIFT;
    float* pm    = pool + O_PM;
    float* pz    = pool + O_PZ;
    float* pa    = pool + O_PA;
    float* xcat  = pool + O_XCAT;
    float* h0    = pool + O_H0;
    float* h1    = pool + O_H1;
    __half* wf = (__half*)(pool + O_WF16);

    // convert all 20 weight matrices to fp16  (arr order: wq,wk,wv,wl1,wl2)
    wconv<<<5120, 256>>>(wq, wk, wv, wl1, wl2, wf);

    const int NT = MROWS / 64;   // 1024 row tiles

    for (int i = 0; i < 4; i++) {
        const float* Qs = i ? Qb[(i - 1) & 1] : q;
        const float* Ks = i ? Kb[(i - 1) & 1] : k;
        const float* Vs = i ? Vb[(i - 1) & 1] : v;
        float* Qd = Qb[i & 1];
        float* Kd = Kb[i & 1];
        float* Vd = Vb[i & 1];

        const __half* whq = wf + (0 * 4 + i) * 65536;
        const __half* whk = wf + (1 * 4 + i) * 65536;
        const __half* whv = wf + (2 * 4 + i) * 65536;
        const __half* wh1 = wf + (3 * 4 + i) * 65536;
        const __half* wh2 = wf + (4 * 4 + i) * 65536;

        gemm_plain<<<NT, 256, GEMM_SMEM>>>(Qs, whq, bq + i * 256, Qd);

        gemm_kv<<<dim3(NT, 2), 256, GEMM_SMEM>>>(
            Ks, whk, bk + i * 256, Kd,
            Vs, whv, bv + i * 256, Vd,
            Qd, W, ssum, ssq);
        bnfinal<<<1, 256>>>(ssum, ssq, g1 + i * 256, be1 + i * 256, scale, shift);

        gemm_bn_stats<<<NT, 256, GEMM_SMEM>>>(W, wh1, bl1 + i * 256,
                                              scale, shift, W2, ssum, ssq);
        bnfinal<<<1, 256>>>(ssum, ssq, g2 + i * 256, be2 + i * 256, scale, shift);

        gemm_bn<<<NT, 256, GEMM_SMEM>>>(W2, wh2, bl2 + i * 256, scale, shift, W);

        smax_part<<<dim3(32, 16), 256>>>(W, Vd, pm, pz, pa);
        smax_comb<<<32, 256>>>(pm, pz, pa, xcat, i);
    }

    mlp_k<<<32, 256>>>(xcat, mw0, mb0, h0, 1024, 1);
    mlp_k<<<32, 256>>>(h0, mw1, mb1, h1, 256, 1);
    mlp_k<<<32, 256>>>(h1, mw2, mb2, (float*)d_out, 256, 0);
}